// round 14
// baseline (speedup 1.0000x reference)
#include <cuda_runtime.h>
#include <cstdint>

// out[b,c,h,w] = x[b,c,2h,2w] * 0.5f     (Haar DWT subband sum collapses to this)
// x:  [16, 64, 512, 512] fp32,  out: [16, 64, 256, 256] fp32
//
// R13 = R8 configuration with 512-thread blocks (CTA-granularity test):
//   - flat grid, 16384 blocks x 512 threads, each block owns 2048 aligned pairs
//   - MLP=4: thread t handles pairs base+t+{0,512,1024,1536}
//   - +512 pairs = +4 output rows = +8 input rows = +1024 float4, so
//     in_idx_k = a0 + 1024k (single decomposition, immediate offsets)
//   - __ldcs loads + __stcs stores (proven optimal in isolation)
//   - fully warp-coalesced: LDG.128 spans 512B/warp, STG.64 spans 256B/warp
//
// Geometry:
//   pair index p in [0, 33'554'432):  out float2 index = p
//   pair = p & 127, orow = (p>>7) & 255, bc = p >> 15
//   input float4 index = bc*65536 + orow*256 + pair   (even input row 2*orow)
//   bc cannot wrap within an aligned 2048-pair block (2048 | 32768).

__global__ __launch_bounds__(512) void haar_sum_kernel(
    const float4* __restrict__ x, float2* __restrict__ out)
{
    const unsigned i0 = blockIdx.x * 2048u + threadIdx.x;

    // single index decomposition
    const unsigned pair = i0 & 127u;
    const unsigned orow = (i0 >> 7) & 255u;
    const unsigned bc   = i0 >> 15;
    const long long a0  = ((long long)bc << 16) + ((long long)orow << 8) + pair;

    // four independent streaming loads (input rows r, r+8, r+16, r+24)
    float4 v0 = __ldcs(&x[a0]);
    float4 v1 = __ldcs(&x[a0 + 1024]);
    float4 v2 = __ldcs(&x[a0 + 2048]);
    float4 v3 = __ldcs(&x[a0 + 3072]);

    float2 o0, o1, o2, o3;
    o0.x = v0.x * 0.5f;  o0.y = v0.z * 0.5f;
    o1.x = v1.x * 0.5f;  o1.y = v1.z * 0.5f;
    o2.x = v2.x * 0.5f;  o2.y = v2.z * 0.5f;
    o3.x = v3.x * 0.5f;  o3.y = v3.z * 0.5f;

    __stcs(&out[i0],         o0);
    __stcs(&out[i0 +  512u], o1);
    __stcs(&out[i0 + 1024u], o2);
    __stcs(&out[i0 + 1536u], o3);
}

extern "C" void kernel_launch(void* const* d_in, const int* in_sizes, int n_in,
                              void* d_out, int out_size)
{
    const float4* x = (const float4*)d_in[0];
    float2* out     = (float2*)d_out;

    // out_size = 67,108,864 floats -> 33,554,432 pairs -> 2048 pairs per block
    long long n_pairs = (long long)out_size / 2;
    long long blocks  = n_pairs / 2048;                // 16384

    haar_sum_kernel<<<(unsigned)blocks, 512>>>(x, out);
}